// round 7
// baseline (speedup 1.0000x reference)
#include <cuda_runtime.h>

#define EMBED 16
// tokens = BATCH * SEQ = 128 * 8192 = 1048576 (divides 256 exactly)

// History:
//   R2: cap 32  -> spills -> 356us
//   R3: cap 255 -> occ 12.5%, latency-bound -> 67us
//   R4: cap 64  -> spills -> 207us
//   R5: fused cos, cap 85 (256,3) -> 39.4us, but L1=85% -> smem-crossbar bound
//       (256 scalar LDS/token on the weight matrix).
//   R6: transpose W in smem; read weight rows as 4x LDS.128 per e
//       -> 64 vector LDS/token (4x fewer crossbar slots).
__global__ __launch_bounds__(256, 3)
void mhaq_kernel(const float* __restrict__ x,
                 const float* __restrict__ theta,
                 const float* __restrict__ w_out,
                 float* __restrict__ y)
{
    __shared__ float s_theta[EMBED];
    __shared__ float4 s_wt[EMBED * 4];   // transposed: s_wt[e*4 + j] = w[o=4j..4j+3][e]

    int tid = threadIdx.x;
    if (tid < EMBED) s_theta[tid] = theta[tid];
    if (tid < EMBED * EMBED) {
        // tid enumerates (o, e); write transposed so o is contiguous per e
        int o = tid / EMBED;
        int e = tid % EMBED;
        reinterpret_cast<float*>(s_wt)[e * EMBED + o] = w_out[o * EMBED + e];
    }
    __syncthreads();

    int token = blockIdx.x * blockDim.x + tid;   // grid sized exactly

    const float4* xv = reinterpret_cast<const float4*>(x) + (size_t)token * 4;
    float4*       yv = reinterpret_cast<float4*>(y) + (size_t)token * 4;

    // 4 independent 128-bit loads -> MLP=4, coalesced 2048B/warp
    float4 a = xv[0];
    float4 b = xv[1];
    float4 c = xv[2];
    float4 d = xv[3];

    float xr[EMBED] = { a.x, a.y, a.z, a.w,
                        b.x, b.y, b.z, b.w,
                        c.x, c.y, c.z, c.w,
                        d.x, d.y, d.z, d.w };

    float acc[EMBED];

    // e = 0: initialize accumulators
    {
        float z0 = __cosf(xr[0] + s_theta[0]);
        #pragma unroll
        for (int j = 0; j < 4; j++) {
            float4 w = s_wt[j];                       // LDS.128, warp-broadcast
            acc[4*j+0] = z0 * w.x;
            acc[4*j+1] = z0 * w.y;
            acc[4*j+2] = z0 * w.z;
            acc[4*j+3] = z0 * w.w;
        }
    }

    // cos fused: one ze live at a time; 4 LDS.128 + 16 FFMA per e
    #pragma unroll
    for (int e = 1; e < EMBED; e++) {
        float ze = __cosf(xr[e] + s_theta[e]);
        #pragma unroll
        for (int j = 0; j < 4; j++) {
            float4 w = s_wt[e * 4 + j];               // LDS.128, warp-broadcast
            acc[4*j+0] = fmaf(ze, w.x, acc[4*j+0]);
            acc[4*j+1] = fmaf(ze, w.y, acc[4*j+1]);
            acc[4*j+2] = fmaf(ze, w.z, acc[4*j+2]);
            acc[4*j+3] = fmaf(ze, w.w, acc[4*j+3]);
        }
    }

    yv[0] = make_float4(acc[ 0], acc[ 1], acc[ 2], acc[ 3]);
    yv[1] = make_float4(acc[ 4], acc[ 5], acc[ 6], acc[ 7]);
    yv[2] = make_float4(acc[ 8], acc[ 9], acc[10], acc[11]);
    yv[3] = make_float4(acc[12], acc[13], acc[14], acc[15]);
}

extern "C" void kernel_launch(void* const* d_in, const int* in_sizes, int n_in,
                              void* d_out, int out_size)
{
    const float* x     = (const float*)d_in[0];   // [B, S, E] = [128, 8192, 16]
    const float* theta = (const float*)d_in[1];   // [E]
    const float* w_out = (const float*)d_in[2];   // [E, E] (o, e)
    float* y           = (float*)d_out;           // [B, S, E]

    int n_tokens = in_sizes[0] / EMBED;           // 1048576, multiple of 256
    int threads = 256;
    int blocks = n_tokens / threads;              // 4096, exact
    mhaq_kernel<<<blocks, threads>>>(x, theta, w_out, y);
}

// round 8
// speedup vs baseline: 1.2159x; 1.2159x over previous
#include <cuda_runtime.h>

#define EMBED 16
// tokens = 128 * 8192 = 1048576 (divides 256 exactly)

// History:
//   R5/R7: 39.4us, L1=85% — smem crossbar wall (~8 wavefronts/token to fan out
//          z*W through shared memory; invariant to scalar-vs-vector LDS width).
//   R8: weights+theta moved to __constant__ (separate const/uniform port, no
//       smem wavefronts). No __shared__ at all. o-outer/e-inner dot products so
//       weight reads are consecutive ld.const.v4 (LDC.128, warp-uniform).
__constant__ float4 c_w4[EMBED * EMBED / 4];   // 64 x float4 = w_out[o][e] row-major
__constant__ float4 c_th4[EMBED / 4];          // theta

__global__ __launch_bounds__(256, 3)
void mhaq_kernel(const float* __restrict__ x, float* __restrict__ y)
{
    int token = blockIdx.x * blockDim.x + threadIdx.x;   // grid sized exactly

    const float4* xv = reinterpret_cast<const float4*>(x) + (size_t)token * 4;
    float4*       yv = reinterpret_cast<float4*>(y)       + (size_t)token * 4;

    // 4 independent 128-bit loads -> MLP=4, coalesced 2048B/warp
    float4 a = xv[0];
    float4 b = xv[1];
    float4 c = xv[2];
    float4 d = xv[3];

    float4 t0 = c_th4[0], t1 = c_th4[1], t2 = c_th4[2], t3 = c_th4[3];

    float z[EMBED];
    z[ 0] = __cosf(a.x + t0.x);  z[ 1] = __cosf(a.y + t0.y);
    z[ 2] = __cosf(a.z + t0.z);  z[ 3] = __cosf(a.w + t0.w);
    z[ 4] = __cosf(b.x + t1.x);  z[ 5] = __cosf(b.y + t1.y);
    z[ 6] = __cosf(b.z + t1.z);  z[ 7] = __cosf(b.w + t1.w);
    z[ 8] = __cosf(c.x + t2.x);  z[ 9] = __cosf(c.y + t2.y);
    z[10] = __cosf(c.z + t2.z);  z[11] = __cosf(c.w + t2.w);
    z[12] = __cosf(d.x + t3.x);  z[13] = __cosf(d.y + t3.y);
    z[14] = __cosf(d.z + t3.z);  z[15] = __cosf(d.w + t3.w);

    // o-outer, e-inner: each output is a 16-term dot; weight reads are
    // consecutive 16B const loads (vectorized, warp-uniform addresses).
    // Two partial sums per output to shorten the FMA dependency chain.
    #pragma unroll
    for (int q = 0; q < 4; q++) {
        float out[4];
        #pragma unroll
        for (int c2 = 0; c2 < 4; c2++) {
            int o = q * 4 + c2;
            float4 w0 = c_w4[o * 4 + 0];
            float4 w1 = c_w4[o * 4 + 1];
            float4 w2 = c_w4[o * 4 + 2];
            float4 w3 = c_w4[o * 4 + 3];

            float s0 = z[0] * w0.x;
            float s1 = z[1] * w0.y;
            s0 = fmaf(z[ 2], w0.z, s0);  s1 = fmaf(z[ 3], w0.w, s1);
            s0 = fmaf(z[ 4], w1.x, s0);  s1 = fmaf(z[ 5], w1.y, s1);
            s0 = fmaf(z[ 6], w1.z, s0);  s1 = fmaf(z[ 7], w1.w, s1);
            s0 = fmaf(z[ 8], w2.x, s0);  s1 = fmaf(z[ 9], w2.y, s1);
            s0 = fmaf(z[10], w2.z, s0);  s1 = fmaf(z[11], w2.w, s1);
            s0 = fmaf(z[12], w3.x, s0);  s1 = fmaf(z[13], w3.y, s1);
            s0 = fmaf(z[14], w3.z, s0);  s1 = fmaf(z[15], w3.w, s1);
            out[c2] = s0 + s1;
        }
        yv[q] = make_float4(out[0], out[1], out[2], out[3]);
    }
}

extern "C" void kernel_launch(void* const* d_in, const int* in_sizes, int n_in,
                              void* d_out, int out_size)
{
    const float* x = (const float*)d_in[0];   // [B, S, E]
    // d_in[1] = theta [16], d_in[2] = w_out [16,16] row-major [o][e]
    float* y = (float*)d_out;

    // Device-to-device async copies into __constant__ — graph-capturable,
    // allocation-free, executed every launch (deterministic).
    cudaMemcpyToSymbolAsync(c_th4, d_in[1], EMBED * sizeof(float), 0,
                            cudaMemcpyDeviceToDevice, 0);
    cudaMemcpyToSymbolAsync(c_w4, d_in[2], EMBED * EMBED * sizeof(float), 0,
                            cudaMemcpyDeviceToDevice, 0);

    int n_tokens = in_sizes[0] / EMBED;       // 1048576, multiple of 256
    int threads = 256;
    int blocks = n_tokens / threads;          // 4096, exact
    mhaq_kernel<<<blocks, threads>>>(x, y);
}